// round 1
// baseline (speedup 1.0000x reference)
#include <cuda_runtime.h>
#include <math.h>

#define NPTS   16384
#define NGRID  4096
#define NNODES 20480
#define GPTS   512
#define HDIM   128
#define DEG    16
#define TFIN   5

// ---------------- scratch (device globals, no allocation) ----------------
__device__ float g_xq[NPTS * 3];
__device__ float g_hq[NPTS * HDIM];
__device__ float g_hg[NGRID * HDIM];
__device__ float g_P[NGRID * HDIM];
__device__ float g_Q[NPTS * HDIM];
__device__ float g_summ[NPTS * HDIM];

__device__ __forceinline__ float silu_f(float x) {
    return x / (1.0f + __expf(-x));
}

#define FMA16(acc, t4p, w) do {                                   \
    float4 _a = (t4p)[0], _b = (t4p)[1], _c = (t4p)[2], _d = (t4p)[3]; \
    acc[0]  = fmaf(_a.x, (w), acc[0]);  acc[1]  = fmaf(_a.y, (w), acc[1]);  \
    acc[2]  = fmaf(_a.z, (w), acc[2]);  acc[3]  = fmaf(_a.w, (w), acc[3]);  \
    acc[4]  = fmaf(_b.x, (w), acc[4]);  acc[5]  = fmaf(_b.y, (w), acc[5]);  \
    acc[6]  = fmaf(_b.z, (w), acc[6]);  acc[7]  = fmaf(_b.w, (w), acc[7]);  \
    acc[8]  = fmaf(_c.x, (w), acc[8]);  acc[9]  = fmaf(_c.y, (w), acc[9]);  \
    acc[10] = fmaf(_c.z, (w), acc[10]); acc[11] = fmaf(_c.w, (w), acc[11]); \
    acc[12] = fmaf(_d.x, (w), acc[12]); acc[13] = fmaf(_d.y, (w), acc[13]); \
    acc[14] = fmaf(_d.z, (w), acc[14]); acc[15] = fmaf(_d.w, (w), acc[15]); \
} while (0)

// ---------------- init: h_query=0, h_grid=codes, x_query=query ----------------
__global__ void init_kernel(const float* __restrict__ qp, const float* __restrict__ codes) {
    int i = blockIdx.x * blockDim.x + threadIdx.x;
    if (i < NPTS * HDIM)  g_hq[i] = 0.0f;
    if (i < NGRID * HDIM) g_hg[i] = codes[i];
    if (i < NPTS * 3)     g_xq[i] = qp[i];
}

// ---------------- projections: P = h_grid @ We1[0:128], Q = h_query @ We1[128:256] --
#define PK 20
__global__ __launch_bounds__(128) void proj_kernel(const float* __restrict__ eW1, int layer) {
    __shared__ float sA[HDIM * PK];
    const int j = threadIdx.x;
    const int base = blockIdx.x * 16;          // 16 rows per block; 16384 % 16 == 0 so no mixed blocks
    const bool isq = (base < NPTS);
    const float* W = eW1 + (size_t)layer * 257 * HDIM + (isq ? 128 * HDIM : 0);

    #pragma unroll
    for (int n = 0; n < 16; ++n) {
        int r = base + n;
        float v = (r < NPTS) ? g_hq[r * HDIM + j] : g_hg[(r - NPTS) * HDIM + j];
        sA[j * PK + n] = v;
    }
    __syncthreads();

    float acc[16];
    #pragma unroll
    for (int n = 0; n < 16; ++n) acc[n] = 0.0f;

    #pragma unroll 4
    for (int k = 0; k < HDIM; ++k) {
        float w = __ldg(&W[k * HDIM + j]);
        const float4* t4 = (const float4*)(sA + k * PK);
        FMA16(acc, t4, w);
    }

    float* outp = isq ? g_Q : g_P;
    int obase = isq ? base : (base - NPTS);
    #pragma unroll
    for (int n = 0; n < 16; ++n) outp[(obase + n) * HDIM + j] = acc[n];
}

// ---------------- edge kernel: 4 query points (64 edges) per block ----------------
#define SE   20
#define SMS  132
template <int TOUT>
__global__ __launch_bounds__(128) void edge_kernel(
    const int*   __restrict__ erow,
    const float* __restrict__ gpts,
    const float* __restrict__ eW1, const float* __restrict__ eb1,
    const float* __restrict__ eW2, const float* __restrict__ eb2,
    const float* __restrict__ coefW, const float* __restrict__ coefB,
    const float* __restrict__ qpts, float* __restrict__ out, int layer)
{
    __shared__ float sT[HDIM * SE];
    __shared__ float sM[DEG * SMS];
    __shared__ float sFc[HDIM * TOUT];
    __shared__ int   sGidx[DEG];
    __shared__ float sDist[DEG], sCm[DEG], sDx[DEG], sDy[DEG], sDz[DEG];

    const int j = threadIdx.x;
    const float wd = __ldg(&eW1[(size_t)layer * 257 * HDIM + 256 * HDIM + j]);
    const float b1 = __ldg(&eb1[layer * HDIM + j]);
    const float b2 = __ldg(&eb2[layer * HDIM + j]);
    const float* W2 = eW2 + (size_t)layer * HDIM * HDIM;

    #pragma unroll
    for (int t = 0; t < TOUT; ++t) sFc[j * TOUT + t] = coefW[j * TOUT + t];

    for (int lq = 0; lq < 4; ++lq) {
        const int q = blockIdx.x * 4 + lq;

        if (j < DEG) {
            int e = j;
            int rv = erow[q * DEG + e];
            int gidx = rv - NPTS;
            int gl = gidx & (GPTS - 1);
            float rx = gpts[gl * 3 + 0] - g_xq[q * 3 + 0];
            float ry = gpts[gl * 3 + 1] - g_xq[q * 3 + 1];
            float rz = gpts[gl * 3 + 2] - g_xq[q * 3 + 2];
            float d = sqrtf(rx * rx + ry * ry + rz * rz);
            float inv = 1.0f / (d + 1e-8f);
            sGidx[e] = gidx; sDist[e] = d;
            sDx[e] = rx * inv; sDy[e] = ry * inv; sDz[e] = rz * inv;
            float cm = 0.5f * (__cosf(d * (float)(M_PI / 10.0)) + 1.0f);
            sCm[e] = (d <= 10.0f) ? cm : 0.0f;
        }
        __syncthreads();

        // stage 1: t[k=j][e] = silu(Q[q][j] + P[gidx_e][j] + dist_e * wd_j + b1_j)
        float Qv = g_Q[q * HDIM + j];
        #pragma unroll
        for (int e = 0; e < DEG; ++e) {
            float pre = Qv + g_P[sGidx[e] * HDIM + j] + sDist[e] * wd + b1;
            sT[j * SE + e] = silu_f(pre);
        }
        __syncthreads();

        // stage 2: m[e][j] = silu( sum_k t[e][k] * We2[k][j] + b2 ) * Cm[e]
        float acc[DEG];
        #pragma unroll
        for (int e = 0; e < DEG; ++e) acc[e] = 0.0f;
        #pragma unroll 4
        for (int k = 0; k < HDIM; ++k) {
            float w = __ldg(&W2[k * HDIM + j]);
            const float4* t4 = (const float4*)(sT + k * SE);
            FMA16(acc, t4, w);
        }

        float msum = 0.0f;
        #pragma unroll
        for (int e = 0; e < DEG; ++e) {
            float mm = silu_f(acc[e] + b2) * sCm[e];
            sM[e * SMS + j] = mm;
            msum += mm;
        }
        if (TOUT == 1) g_summ[q * HDIM + j] = msum * (1.0f / DEG);
        __syncthreads();

        // stage 3: coef per edge, then reduce cmsg over the 16 edges
        if (j < DEG) {
            const int e = j;
            float coef[TOUT];
            #pragma unroll
            for (int t = 0; t < TOUT; ++t) coef[t] = coefB[t];
            const float4* mr = (const float4*)(sM + e * SMS);
            #pragma unroll
            for (int k4 = 0; k4 < HDIM / 4; ++k4) {
                float4 mv = mr[k4];
                #pragma unroll
                for (int t = 0; t < TOUT; ++t) {
                    coef[t] = fmaf(mv.x, sFc[(k4 * 4 + 0) * TOUT + t],
                              fmaf(mv.y, sFc[(k4 * 4 + 1) * TOUT + t],
                              fmaf(mv.z, sFc[(k4 * 4 + 2) * TOUT + t],
                              fmaf(mv.w, sFc[(k4 * 4 + 3) * TOUT + t], coef[t]))));
                }
            }
            float dir[3] = { sDx[e], sDy[e], sDz[e] };
            #pragma unroll
            for (int t = 0; t < TOUT; ++t) {
                #pragma unroll
                for (int d = 0; d < 3; ++d) {
                    float v = coef[t] * dir[d];
                    v += __shfl_down_sync(0x0000FFFFu, v, 8);
                    v += __shfl_down_sync(0x0000FFFFu, v, 4);
                    v += __shfl_down_sync(0x0000FFFFu, v, 2);
                    v += __shfl_down_sync(0x0000FFFFu, v, 1);
                    if (e == 0) {
                        if (TOUT == 1) {
                            g_xq[q * 3 + d] += v * (1.0f / DEG);
                        } else {
                            out[(q * TFIN + t) * 3 + d] =
                                (g_xq[q * 3 + d] - qpts[q * 3 + d]) + v * (1.0f / DEG);
                        }
                    }
                }
            }
        }
        __syncthreads();
    }
}

// ---------------- node kernel: h += silu([h, m_aggr] @ Wn1 + b1) @ Wn2 + b2 --------
#define SP 20
__global__ __launch_bounds__(128) void node_kernel(
    const float* __restrict__ nW1, const float* __restrict__ nb1,
    const float* __restrict__ nW2, const float* __restrict__ nb2, int layer)
{
    __shared__ float sIn[256 * SP];
    __shared__ float sU[HDIM * SP];
    const int j = threadIdx.x;
    const int base = blockIdx.x * 16;
    const float* W1 = nW1 + (size_t)layer * 256 * HDIM;
    const float* W2 = nW2 + (size_t)layer * HDIM * HDIM;
    const float bb1 = __ldg(&nb1[layer * HDIM + j]);
    const float bb2 = __ldg(&nb2[layer * HDIM + j]);

    #pragma unroll
    for (int n = 0; n < 16; ++n) {
        int node = base + n;
        float hv, mv;
        if (node < NPTS) { hv = g_hq[node * HDIM + j]; mv = g_summ[node * HDIM + j]; }
        else             { hv = g_hg[(node - NPTS) * HDIM + j]; mv = 0.0f; }
        sIn[j * SP + n] = hv;
        sIn[(128 + j) * SP + n] = mv;
    }
    __syncthreads();

    float acc[16];
    #pragma unroll
    for (int n = 0; n < 16; ++n) acc[n] = 0.0f;
    #pragma unroll 4
    for (int k = 0; k < 256; ++k) {
        float w = __ldg(&W1[k * HDIM + j]);
        const float4* t4 = (const float4*)(sIn + k * SP);
        FMA16(acc, t4, w);
    }
    #pragma unroll
    for (int n = 0; n < 16; ++n) sU[j * SP + n] = silu_f(acc[n] + bb1);
    __syncthreads();

    #pragma unroll
    for (int n = 0; n < 16; ++n) acc[n] = 0.0f;
    #pragma unroll 4
    for (int k = 0; k < HDIM; ++k) {
        float w = __ldg(&W2[k * HDIM + j]);
        const float4* t4 = (const float4*)(sU + k * SP);
        FMA16(acc, t4, w);
    }
    #pragma unroll
    for (int n = 0; n < 16; ++n) {
        int node = base + n;
        float hnew = sIn[j * SP + n] + acc[n] + bb2;
        if (node < NPTS) g_hq[node * HDIM + j] = hnew;
        else             g_hg[(node - NPTS) * HDIM + j] = hnew;
    }
}

// ---------------- launch ----------------
extern "C" void kernel_launch(void* const* d_in, const int* in_sizes, int n_in,
                              void* d_out, int out_size) {
    const float* qp    = (const float*)d_in[0];
    const float* codes = (const float*)d_in[1];
    const float* gpts  = (const float*)d_in[2];
    const float* eW1   = (const float*)d_in[3];
    const float* eb1   = (const float*)d_in[4];
    const float* eW2   = (const float*)d_in[5];
    const float* eb2   = (const float*)d_in[6];
    const float* cW    = (const float*)d_in[7];
    const float* cb    = (const float*)d_in[8];
    const float* fcW   = (const float*)d_in[9];
    const float* fcb   = (const float*)d_in[10];
    const float* nW1   = (const float*)d_in[11];
    const float* nb1   = (const float*)d_in[12];
    const float* nW2   = (const float*)d_in[13];
    const float* nb2   = (const float*)d_in[14];
    const int*   eidx  = (const int*)d_in[15];
    float* out = (float*)d_out;

    init_kernel<<<(NPTS * HDIM + 255) / 256, 256>>>(qp, codes);

    for (int L = 0; L < 4; ++L) {
        proj_kernel<<<NNODES / 16, 128>>>(eW1, L);
        if (L < 3) {
            edge_kernel<1><<<NPTS / 4, 128>>>(eidx, gpts, eW1, eb1, eW2, eb2,
                                              cW + L * HDIM, cb + L, qp, nullptr, L);
            node_kernel<<<NNODES / 16, 128>>>(nW1, nb1, nW2, nb2, L);
        } else {
            edge_kernel<TFIN><<<NPTS / 4, 128>>>(eidx, gpts, eW1, eb1, eW2, eb2,
                                                 fcW, fcb, qp, out, L);
        }
    }
}